// round 6
// baseline (speedup 1.0000x reference)
#include <cuda_runtime.h>
#include <cstddef>

// GraphSage gather + cosine top-16 + mean.  (Round 6)
//   d_in[0] nodes  : int32 [N]
//   d_in[1] neigh  : int32 [N, 32]
//   d_in[2] u2e_visual : f32 [500000, 64]
//   d_in[3] u2e_text   : f32 [500000, 64]
// Output: f32 concat(u_v, u_t, v_agg, t_agg), each [N, 64].
//
// One warp per (node, modality), modality-major order (single-table L2 phase).
// Each 8-lane group owns neighbors 8g..8g+7 and KEEPS their rows in registers
// (float4 va[8], vb[8]); the mean phase is pure register math (zero loads),
// cutting ~30% of L1 wavefronts. All 16 row loads issue before any consume
// (MLP=16 -> one long-scoreboard stall per warp). Sim reduction: R3-style
// independent per-neighbor butterflies (best ILP). Contiguous mapping lands
// sim(L) on lane L with no redistribute. Ranking via dot*|dot|/||v||^2
// (strictly monotone in cosine), stable top-16 rank count.

#define DEG   32
#define TOPK  16
#define EMB   64

__global__ __launch_bounds__(128, 5) void gs_kernel(
    const int*   __restrict__ nodes,
    const int*   __restrict__ neigh,
    const float* __restrict__ uv,
    const float* __restrict__ ut,
    float*       __restrict__ out,
    int n)
{
    const unsigned FULL = 0xffffffffu;
    int wg = (int)((blockIdx.x * blockDim.x + threadIdx.x) >> 5);
    if (wg >= 2 * n) return;
    int lane = threadIdx.x & 31;

    // modality-major task order: [0,n) = visual, [n,2n) = text
    int m    = (wg >= n) ? 1 : 0;
    int node = wg - m * n;
    const float* __restrict__ emb = m ? ut : uv;

    int g = lane >> 3;     // 8-lane group id (0..3): owns neighbors 8g..8g+7
    int s = lane & 7;      // sub-lane within group

    // ---- center gather (lane s holds float4 s and s+8 of the row) ----
    int cidx = __ldcs(nodes + node);
    const float4* crow = (const float4*)(emb + (size_t)cidx * EMB);
    float4 ua = __ldg(crow + s);
    float4 ub = __ldg(crow + s + 8);

    size_t nn = (size_t)n * EMB;
    float4* cout = (float4*)(out + (size_t)m * nn + (size_t)node * EMB);
    if (g == 0) { __stcs(cout + s, ua); __stcs(cout + s + 8, ub); }

    // ---- neighbor indices: lane k holds neigh[node][k] ----
    int nidx = __ldcs(neigh + (size_t)node * DEG + lane);

    // ---- load all 8 rows of this group up-front (16 LDG.128 in flight) ----
    float4 va[8], vb[8];
    #pragma unroll
    for (int t = 0; t < 8; t++) {
        int j = __shfl_sync(FULL, nidx, 8 * g + t);
        const float4* vrow = (const float4*)(emb + (size_t)j * EMB);
        va[t] = __ldg(vrow + s);
        vb[t] = __ldg(vrow + s + 8);
    }

    // ---- per-neighbor dot/nsq + independent 3-step butterflies ----
    float fd = 0.0f, fn = 1.0f;   // this lane's neighbor's reduced values
    #pragma unroll
    for (int t = 0; t < 8; t++) {
        float dot = va[t].x * ua.x + va[t].y * ua.y + va[t].z * ua.z + va[t].w * ua.w
                  + vb[t].x * ub.x + vb[t].y * ub.y + vb[t].z * ub.z + vb[t].w * ub.w;
        float nsq = va[t].x * va[t].x + va[t].y * va[t].y + va[t].z * va[t].z + va[t].w * va[t].w
                  + vb[t].x * vb[t].x + vb[t].y * vb[t].y + vb[t].z * vb[t].z + vb[t].w * vb[t].w;
        #pragma unroll
        for (int d = 1; d < 8; d <<= 1) {
            dot += __shfl_xor_sync(FULL, dot, d);
            nsq += __shfl_xor_sync(FULL, nsq, d);
        }
        if (s == t) { fd = dot; fn = nsq; }   // lane 8g+t keeps neighbor 8g+t
    }

    // ranking value: dot*|dot|/||v||^2 — strictly monotone in cosine
    // (center norm is a positive per-node constant, irrelevant to order).
    float mysim = __fdividef(fd * fabsf(fd), fn + 1e-20f);

    // ---- stable top-16 via rank count (matches jax.lax.top_k tie-break) ----
    int cnt = 0;
    #pragma unroll
    for (int d = 1; d < DEG; d++) {
        float o = __shfl_xor_sync(FULL, mysim, d);
        int jl = lane ^ d;
        cnt += (o > mysim) || (o == mysim && jl < lane);
    }
    unsigned sel = __ballot_sync(FULL, cnt < TOPK);   // exactly TOPK bits set

    // ---- mean of selected rows: pure register math, zero loads ----
    unsigned selg = (sel >> (8 * g)) & 0xffu;
    float4 aA = make_float4(0.f, 0.f, 0.f, 0.f);
    float4 aB = make_float4(0.f, 0.f, 0.f, 0.f);
    #pragma unroll
    for (int t = 0; t < 8; t++) {
        if (selg & (1u << t)) {
            aA.x += va[t].x; aA.y += va[t].y; aA.z += va[t].z; aA.w += va[t].w;
            aB.x += vb[t].x; aB.y += vb[t].y; aB.z += vb[t].z; aB.w += vb[t].w;
        }
    }
    // combine the 4 groups' partial row-sums (each laid out over 8 lanes)
    #pragma unroll
    for (int d = 8; d <= 16; d <<= 1) {
        aA.x += __shfl_xor_sync(FULL, aA.x, d);
        aA.y += __shfl_xor_sync(FULL, aA.y, d);
        aA.z += __shfl_xor_sync(FULL, aA.z, d);
        aA.w += __shfl_xor_sync(FULL, aA.w, d);
        aB.x += __shfl_xor_sync(FULL, aB.x, d);
        aB.y += __shfl_xor_sync(FULL, aB.y, d);
        aB.z += __shfl_xor_sync(FULL, aB.z, d);
        aB.w += __shfl_xor_sync(FULL, aB.w, d);
    }

    if (g == 0) {
        const float sc = 1.0f / (float)TOPK;
        float4* aout = (float4*)(out + (size_t)(2 + m) * nn + (size_t)node * EMB);
        float4 rA = make_float4(aA.x * sc, aA.y * sc, aA.z * sc, aA.w * sc);
        float4 rB = make_float4(aB.x * sc, aB.y * sc, aB.z * sc, aB.w * sc);
        __stcs(aout + s, rA);
        __stcs(aout + s + 8, rB);
    }
}

extern "C" void kernel_launch(void* const* d_in, const int* in_sizes, int n_in,
                              void* d_out, int out_size) {
    const int*   nodes = (const int*)d_in[0];
    const int*   neigh = (const int*)d_in[1];
    const float* uv    = (const float*)d_in[2];
    const float* ut    = (const float*)d_in[3];
    float*       out   = (float*)d_out;
    int n = in_sizes[0];
    int warps = 2 * n;
    int threads = 128;
    int blocks = (warps * 32 + threads - 1) / threads;
    gs_kernel<<<blocks, threads>>>(nodes, neigh, uv, ut, out, n);
}

// round 7
// speedup vs baseline: 1.0111x; 1.0111x over previous
#include <cuda_runtime.h>
#include <cstddef>

// GraphSage gather + cosine top-16 + mean.  (Round 7)
//   d_in[0] nodes  : int32 [N]
//   d_in[1] neigh  : int32 [N, 32]
//   d_in[2] u2e_visual : f32 [500000, 64]
//   d_in[3] u2e_text   : f32 [500000, 64]
// Output: f32 concat(u_v, u_t, v_agg, t_agg), each [N, 64].
//
// One warp per (node, modality), modality-major order (single-table L2 phase).
// Sim: 8-lane groups, group g owns neighbors 8g..8g+7 (sim lands on lane L,
// no redistribute). Independent per-neighbor butterflies (best ILP, R3-proven).
// Selection: bitonic sort of the 32 rank values + threshold at the 16th
// largest; among equals the lowest indices win => identical to stable top_k.
// Mean: 16-lane halves over the selected rows (L1-resident re-reads).
// Ranking value dot*|dot|/||v||^2 (strictly monotone in cosine; center norm
// is a positive per-node constant). Streams use evict-first hints.

#define DEG   32
#define TOPK  16
#define EMB   64

__global__ __launch_bounds__(256, 7) void gs_kernel(
    const int*   __restrict__ nodes,
    const int*   __restrict__ neigh,
    const float* __restrict__ uv,
    const float* __restrict__ ut,
    float*       __restrict__ out,
    int n)
{
    const unsigned FULL = 0xffffffffu;
    int wg = (int)((blockIdx.x * blockDim.x + threadIdx.x) >> 5);
    if (wg >= 2 * n) return;
    int lane = threadIdx.x & 31;

    // modality-major task order: [0,n) = visual, [n,2n) = text
    int m    = (wg >= n) ? 1 : 0;
    int node = wg - m * n;
    const float* __restrict__ emb = m ? ut : uv;

    int g = lane >> 3;     // 8-lane group id (0..3): owns neighbors 8g..8g+7
    int s = lane & 7;      // sub-lane within group

    // ---- center gather (lane s holds float4 s and s+8 of the row) ----
    int cidx = __ldcs(nodes + node);
    const float4* crow = (const float4*)(emb + (size_t)cidx * EMB);
    float4 ua = __ldg(crow + s);
    float4 ub = __ldg(crow + s + 8);

    size_t nn = (size_t)n * EMB;
    float4* cout = (float4*)(out + (size_t)m * nn + (size_t)node * EMB);
    if (g == 0) { __stcs(cout + s, ua); __stcs(cout + s + 8, ub); }

    // ---- neighbor indices: lane k holds neigh[node][k] ----
    int nidx = __ldcs(neigh + (size_t)node * DEG + lane);

    // ---- rank value per neighbor: dot*|dot|/||v||^2 (monotone in cosine) ----
    float fd = 0.0f, fn = 1.0f;
    #pragma unroll
    for (int t = 0; t < 8; t++) {
        int j = __shfl_sync(FULL, nidx, 8 * g + t);
        const float4* vrow = (const float4*)(emb + (size_t)j * EMB);
        float4 va = __ldg(vrow + s);
        float4 vb = __ldg(vrow + s + 8);
        float dot = va.x * ua.x + va.y * ua.y + va.z * ua.z + va.w * ua.w
                  + vb.x * ub.x + vb.y * ub.y + vb.z * ub.z + vb.w * ub.w;
        float nsq = va.x * va.x + va.y * va.y + va.z * va.z + va.w * va.w
                  + vb.x * vb.x + vb.y * vb.y + vb.z * vb.z + vb.w * vb.w;
        #pragma unroll
        for (int d = 1; d < 8; d <<= 1) {        // independent 3-step butterflies
            dot += __shfl_xor_sync(FULL, dot, d);
            nsq += __shfl_xor_sync(FULL, nsq, d);
        }
        if (s == t) { fd = dot; fn = nsq; }      // lane 8g+t keeps neighbor 8g+t
    }
    float mysim = __fdividef(fd * fabsf(fd), fn + 1e-20f);

    // ---- bitonic sort (ascending across the warp) to find the threshold ----
    float v = mysim;
    #pragma unroll
    for (int k2 = 2; k2 <= 32; k2 <<= 1) {
        #pragma unroll
        for (int j2 = k2 >> 1; j2 > 0; j2 >>= 1) {
            float o  = __shfl_xor_sync(FULL, v, j2);
            bool up    = ((lane & k2) == 0);     // ascending block
            bool upper = ((lane & j2) != 0);     // upper element of the pair
            float lo = fminf(v, o), hi = fmaxf(v, o);
            v = (upper == up) ? hi : lo;
        }
    }
    float T = __shfl_sync(FULL, v, 16);          // 16th-largest value

    // ---- stable top-16: all >T, then lowest-index ==T (matches top_k) ----
    unsigned gt = __ballot_sync(FULL, mysim > T);
    unsigned eq = __ballot_sync(FULL, mysim == T);
    int need = TOPK - __popc(gt);                // >=1 by construction
    bool sel_me = (mysim > T) ||
                  ((mysim == T) && (__popc(eq & ((1u << lane) - 1)) < need));
    unsigned sel = __ballot_sync(FULL, sel_me);  // exactly TOPK bits set

    // ---- mean of selected (unnormalized) rows; re-reads hit L1 ----
    int half = lane >> 4;   // 16-lane halves: 2 neighbors per iteration
    int sub  = lane & 15;
    float4 acc = make_float4(0.f, 0.f, 0.f, 0.f);
    #pragma unroll
    for (int k = 0; k < DEG; k += 2) {
        int kk = k + half;
        int j = __shfl_sync(FULL, nidx, kk);
        if (sel & (1u << kk)) {
            float4 vv = __ldg((const float4*)(emb + (size_t)j * EMB) + sub);
            acc.x += vv.x; acc.y += vv.y; acc.z += vv.z; acc.w += vv.w;
        }
    }
    acc.x += __shfl_xor_sync(FULL, acc.x, 16);
    acc.y += __shfl_xor_sync(FULL, acc.y, 16);
    acc.z += __shfl_xor_sync(FULL, acc.z, 16);
    acc.w += __shfl_xor_sync(FULL, acc.w, 16);

    if (half == 0) {
        const float sc = 1.0f / (float)TOPK;
        float4 r = make_float4(acc.x * sc, acc.y * sc, acc.z * sc, acc.w * sc);
        float4* aout = (float4*)(out + (size_t)(2 + m) * nn + (size_t)node * EMB);
        __stcs(aout + sub, r);
    }
}

extern "C" void kernel_launch(void* const* d_in, const int* in_sizes, int n_in,
                              void* d_out, int out_size) {
    const int*   nodes = (const int*)d_in[0];
    const int*   neigh = (const int*)d_in[1];
    const float* uv    = (const float*)d_in[2];
    const float* ut    = (const float*)d_in[3];
    float*       out   = (float*)d_out;
    int n = in_sizes[0];
    int warps = 2 * n;
    int threads = 256;
    int blocks = (warps * 32 + threads - 1) / threads;
    gs_kernel<<<blocks, threads>>>(nodes, neigh, uv, ut, out, n);
}